// round 15
// baseline (speedup 1.0000x reference)
#include <cuda_runtime.h>
#include <mma.h>
#include <math.h>
#include <stdint.h>

using namespace nvcuda;

#define SEQ    2048
#define DM     1024
#define DH     64
#define NH     16
#define DFF    4096
#define NB     12
#define VOCAB  50257
#define LN_EPS 1e-5f

// ---------------- device scratch ----------------
__device__ float g_x   [SEQ * DM];
__device__ float g_q   [SEQ * DM];
__device__ float g_k   [SEQ * DM];
__device__ float g_v   [SEQ * DM];
__device__ float g_attn[(size_t)NH * SEQ * SEQ];
__device__ float g_mha [SEQ * DM];
__device__ float g_ff  [SEQ * DFF];
__device__ float g_t2  [SEQ * DM];

// ---------------- helpers ----------------
__device__ __forceinline__ uint32_t smem_u32(const void* p) {
    uint32_t a;
    asm("{ .reg .u64 t; cvta.to.shared.u64 t, %1; cvt.u32.u64 %0, t; }" : "=r"(a) : "l"(p));
    return a;
}
__device__ __forceinline__ float tf32r(float x) {
    uint32_t u;
    asm("cvt.rna.tf32.f32 %0, %1;" : "=r"(u) : "f"(x));
    return __uint_as_float(u);
}
__device__ __forceinline__ void cp16(uint32_t dst, const void* src) {
    asm volatile("cp.async.cg.shared.global [%0], [%1], 16;"
                 :: "r"(dst), "l"(src) : "memory");
}
__device__ __forceinline__ void cp4(uint32_t dst, const void* src) {
    asm volatile("cp.async.ca.shared.global [%0], [%1], 4;"
                 :: "r"(dst), "l"(src) : "memory");
}
__device__ __forceinline__ void cp_commit() {
    asm volatile("cp.async.commit_group;" ::: "memory");
}
__device__ __forceinline__ void cp_wait2() {
    asm volatile("cp.async.wait_group 2;" ::: "memory");
}

typedef wmma::fragment<wmma::matrix_a, 16, 16, 8, wmma::precision::tf32, wmma::row_major> FragA;
typedef wmma::fragment<wmma::matrix_b, 16, 16, 8, wmma::precision::tf32, wmma::row_major> FragBR;
typedef wmma::fragment<wmma::matrix_b, 16, 16, 8, wmma::precision::tf32, wmma::col_major> FragBC;
typedef wmma::fragment<wmma::accumulator, 16, 16, 8, float> FragC;

template <class F>
__device__ __forceinline__ void split_frag(const F& raw, F& hi, F& lo) {
    #pragma unroll
    for (int i = 0; i < raw.num_elements; ++i) {
        float x = raw.x[i];
        float h = tf32r(x);
        hi.x[i] = h;
        lo.x[i] = tf32r(x - h);
    }
}

// ============================================================================
// 3xTF32 mma.sync GEMM.  C[m,n] (+bias)(relu)(scale) = sum_k A[m,k]*B[k,n]
// Block tile 128m x 64n, BK=16, 3-stage cp.async pipeline, 8 warps (32x32 each).
// BMODE: 0 = B row-major [K,N]
//        1 = B head-blocked QKV weights: B[k, n] at W[(n>>6)*DM*64 + k*64 + (n&63)]
//        2 = B stored [N,K] (we need B^T; fragments loaded col-major)
// BV4  : 16B-vectorizable B rows (ldb%4==0 and no OOB columns)
// CSKIP: skip tiles fully above causal diagonal (scores)
// KCLIP: Keff = min(K, m0+128) (attn probs are zero beyond the diagonal band)
// ============================================================================
#define BKC    16
#define STG    3
#define LDA_S  24          // A smem row stride (floats); also mode2 B
#define LDB_S  72          // row-major B smem row stride
#define LDE    72          // epilogue staging stride
#define ASZ    (128 * LDA_S)          // 3072 floats / stage
#define BSLOT  (64 * LDA_S)           // 1536 floats / stage (max of modes)
#define SMEMSZ ((STG * (ASZ + BSLOT)) * 4 + 128)

template <int BMODE, bool BV4, bool RELU, bool CSKIP, bool KCLIP>
__global__ void __launch_bounds__(256, 2) tc_gemm(
    const float* __restrict__ A, const float* __restrict__ B,
    const float* __restrict__ bias, float* __restrict__ C,
    int N, int K, int lda, int ldb, int ldc,
    long long zA, long long zB, long long zC, float scale)
{
    const int m0 = blockIdx.y * 128;
    const int n0 = blockIdx.x * 64;
    if (CSKIP && n0 > m0 + 127) return;

    A += (long long)blockIdx.z * zA;
    B += (long long)blockIdx.z * zB;
    C += (long long)blockIdx.z * zC;

    // mode1: whole 64-wide tile lives in one head block -> plain row-major, ldb=64
    int ldbe = ldb, nbase = n0;
    if (BMODE == 1) { B += (size_t)(n0 >> 6) * (DM * 64); ldbe = 64; nbase = 0; }

    extern __shared__ char dsm[];
    const uint32_t raw  = smem_u32(dsm);
    const uint32_t base = (raw + 127u) & ~127u;
    float* sA = (float*)(dsm + (base - raw));
    float* sB = sA + STG * ASZ;
    const uint32_t sAu = base;
    const uint32_t sBu = base + STG * ASZ * 4;

    const int tid = threadIdx.x;
    const int wid = tid >> 5;
    const int wm  = wid >> 1;      // 0..3 -> m offset wm*32
    const int wn  = wid & 1;       // 0..1 -> n offset wn*32

    int Keff = K;
    if (KCLIP) { int km = m0 + 128; Keff = km < K ? km : K; }
    const int nch = Keff / BKC;

    FragC acc[2][2];
    #pragma unroll
    for (int i = 0; i < 2; ++i)
        #pragma unroll
        for (int j = 0; j < 2; ++j)
            wmma::fill_fragment(acc[i][j], 0.0f);

    // ---------------- stage loader ----------------
    auto load_stage = [&](int ch) {
        if (ch < nch) {
            const int st = ch % STG;
            const int k0 = ch * BKC;
            const uint32_t au = sAu + st * (ASZ * 4);
            // A tile: 128 rows x 16 floats, 512 16B chunks, 2/thread
            #pragma unroll
            for (int i = 0; i < 2; ++i) {
                int c  = tid + (i << 8);
                int r  = c >> 2;
                int k4 = (c & 3) << 2;
                cp16(au + (uint32_t)(r * LDA_S + k4) * 4,
                     A + (size_t)(m0 + r) * lda + k0 + k4);
            }
            const uint32_t bu = sBu + st * (BSLOT * 4);
            if (BMODE == 2) {
                // B^T tile: 64 rows (n) x 16 floats (k)
                int c  = tid;
                int r  = c >> 2;
                int k4 = (c & 3) << 2;
                cp16(bu + (uint32_t)(r * LDA_S + k4) * 4,
                     B + (size_t)(n0 + r) * ldb + k0 + k4);
            } else if (BV4) {
                // row-major B tile: 16 rows (k) x 64 floats (n)
                int c  = tid;
                int r  = c >> 4;
                int n4 = (c & 15) << 2;
                cp16(bu + (uint32_t)(r * LDB_S + n4) * 4,
                     B + (size_t)(k0 + r) * ldbe + nbase + n4);
            } else {
                // scalar path (unaligned ldb / ragged N) — OOB columns skipped;
                // stale smem only pollutes output columns >= N (never stored)
                #pragma unroll
                for (int i = 0; i < 4; ++i) {
                    int c = tid + (i << 8);
                    int r = c >> 6;
                    int n = c & 63;
                    if (n0 + n < N)
                        cp4(bu + (uint32_t)(r * LDB_S + n) * 4,
                            B + (size_t)(k0 + r) * ldb + n0 + n);
                }
            }
        }
        cp_commit();
    };

    // ---------------- stage compute ----------------
    auto compute_stage = [&](int st) {
        const float* Ab = sA + st * ASZ + (wm * 32) * LDA_S;
        const float* Bb = sB + st * BSLOT;
        #pragma unroll
        for (int ks = 0; ks < 2; ++ks) {
            FragA a_hi[2], a_lo[2];
            #pragma unroll
            for (int i = 0; i < 2; ++i) {
                FragA ar;
                wmma::load_matrix_sync(ar, Ab + i * 16 * LDA_S + ks * 8, LDA_S);
                split_frag(ar, a_hi[i], a_lo[i]);
            }
            if constexpr (BMODE == 2) {
                FragBC b_hi[2], b_lo[2];
                #pragma unroll
                for (int j = 0; j < 2; ++j) {
                    FragBC br;
                    wmma::load_matrix_sync(br, Bb + (wn * 32 + j * 16) * LDA_S + ks * 8, LDA_S);
                    split_frag(br, b_hi[j], b_lo[j]);
                }
                #pragma unroll
                for (int i = 0; i < 2; ++i)
                    #pragma unroll
                    for (int j = 0; j < 2; ++j) {
                        wmma::mma_sync(acc[i][j], a_hi[i], b_hi[j], acc[i][j]);
                        wmma::mma_sync(acc[i][j], a_hi[i], b_lo[j], acc[i][j]);
                        wmma::mma_sync(acc[i][j], a_lo[i], b_hi[j], acc[i][j]);
                    }
            } else {
                FragBR b_hi[2], b_lo[2];
                #pragma unroll
                for (int j = 0; j < 2; ++j) {
                    FragBR br;
                    wmma::load_matrix_sync(br, Bb + ks * 8 * LDB_S + wn * 32 + j * 16, LDB_S);
                    split_frag(br, b_hi[j], b_lo[j]);
                }
                #pragma unroll
                for (int i = 0; i < 2; ++i)
                    #pragma unroll
                    for (int j = 0; j < 2; ++j) {
                        wmma::mma_sync(acc[i][j], a_hi[i], b_hi[j], acc[i][j]);
                        wmma::mma_sync(acc[i][j], a_hi[i], b_lo[j], acc[i][j]);
                        wmma::mma_sync(acc[i][j], a_lo[i], b_hi[j], acc[i][j]);
                    }
            }
        }
    };

    // ---------------- pipelined main loop ----------------
    load_stage(0);
    load_stage(1);
    for (int ch = 0; ch < nch; ++ch) {
        load_stage(ch + 2);
        cp_wait2();
        __syncthreads();
        compute_stage(ch % STG);
        __syncthreads();
    }

    // ---------------- epilogue: acc -> smem staging -> coalesced gmem ----------------
    float* epf = sA;   // reuse (128 x 72 = 9216 floats = ASZ*3 exactly fits)
    #pragma unroll
    for (int i = 0; i < 2; ++i)
        #pragma unroll
        for (int j = 0; j < 2; ++j)
            wmma::store_matrix_sync(epf + (size_t)(wm * 32 + i * 16) * LDE + wn * 32 + j * 16,
                                    acc[i][j], LDE, wmma::mem_row_major);
    __syncthreads();

    {
        const int qid  = tid & 15;          // 16 column quads
        const int rbeg = tid >> 4;          // 16 row groups
        const int col  = n0 + (qid << 2);

        float4 bv = make_float4(0.f, 0.f, 0.f, 0.f);
        if (bias) {
            if (col + 0 < N) bv.x = bias[col + 0];
            if (col + 1 < N) bv.y = bias[col + 1];
            if (col + 2 < N) bv.z = bias[col + 2];
            if (col + 3 < N) bv.w = bias[col + 3];
        }
        const bool v4 = ((ldc & 3) == 0) && (col + 3 < N);

        for (int r = rbeg; r < 128; r += 16) {
            float4 v = *(float4*)(epf + (size_t)r * LDE + (qid << 2));
            v.x = v.x * scale + bv.x; v.y = v.y * scale + bv.y;
            v.z = v.z * scale + bv.z; v.w = v.w * scale + bv.w;
            if (RELU) {
                v.x = fmaxf(v.x, 0.f); v.y = fmaxf(v.y, 0.f);
                v.z = fmaxf(v.z, 0.f); v.w = fmaxf(v.w, 0.f);
            }
            float* Cp = C + (size_t)(m0 + r) * ldc + col;
            if (v4) {
                *(float4*)Cp = v;
            } else {
                if (col + 0 < N) Cp[0] = v.x;
                if (col + 1 < N) Cp[1] = v.y;
                if (col + 2 < N) Cp[2] = v.z;
                if (col + 3 < N) Cp[3] = v.w;
            }
        }
    }
}

// ---------------- embedding + sinusoidal PE ----------------
__global__ void embed_kernel(const int* __restrict__ tokens,
                             const float* __restrict__ emb)
{
    int s = blockIdx.x;
    int tok = tokens[s];
    const float* e = emb + (size_t)tok * DM;
    for (int d = threadIdx.x; d < DM; d += blockDim.x) {
        int iv = d & ~1;
        double ang = (double)s * pow(10000.0, -(double)iv / (double)DM);
        float pe = (d & 1) ? (float)cos(ang) : (float)sin(ang);
        g_x[s * DM + d] = e[d] + pe;
    }
}

// ---------------- causal row softmax (zero-fills only the diagonal band) ----------------
__global__ void softmax_kernel()
{
    const int s = blockIdx.x, h = blockIdx.y, tid = threadIdx.x;
    float* row = g_attn + ((size_t)h * SEQ + s) * SEQ;
    const int len = s + 1;
    const int band = ((s >> 7) + 1) << 7;   // AV K-clip reads cols < band only

    __shared__ float red[256];

    float m = -1e30f;
    for (int t = tid; t < len; t += 256) m = fmaxf(m, row[t]);
    red[tid] = m; __syncthreads();
    for (int st = 128; st; st >>= 1) { if (tid < st) red[tid] = fmaxf(red[tid], red[tid + st]); __syncthreads(); }
    m = red[0]; __syncthreads();

    float sum = 0.f;
    for (int t = tid; t < len; t += 256) { float e = __expf(row[t] - m); row[t] = e; sum += e; }
    red[tid] = sum; __syncthreads();
    for (int st = 128; st; st >>= 1) { if (tid < st) red[tid] += red[tid + st]; __syncthreads(); }
    const float inv = 1.0f / red[0];

    for (int t = tid; t < len; t += 256) row[t] *= inv;
    for (int t = len + tid; t < band; t += 256) row[t] = 0.f;
}

// ---------------- fused residual + LayerNorm ----------------
__global__ void ln_kernel(const float* __restrict__ branch,
                          const float* __restrict__ g,
                          const float* __restrict__ b)
{
    const int s = blockIdx.x, tid = threadIdx.x;
    __shared__ float red[256];

    float v[4];
    float sum = 0.f;
    #pragma unroll
    for (int r = 0; r < 4; ++r) {
        int d = tid + r * 256;
        v[r] = g_x[s * DM + d] + branch[s * DM + d];
        sum += v[r];
    }
    red[tid] = sum; __syncthreads();
    for (int st = 128; st; st >>= 1) { if (tid < st) red[tid] += red[tid + st]; __syncthreads(); }
    const float mu = red[0] * (1.0f / DM);
    __syncthreads();

    float sq = 0.f;
    #pragma unroll
    for (int r = 0; r < 4; ++r) { float d0 = v[r] - mu; sq += d0 * d0; }
    red[tid] = sq; __syncthreads();
    for (int st = 128; st; st >>= 1) { if (tid < st) red[tid] += red[tid + st]; __syncthreads(); }
    const float rstd = rsqrtf(red[0] * (1.0f / DM) + LN_EPS);

    #pragma unroll
    for (int r = 0; r < 4; ++r) {
        int d = tid + r * 256;
        g_x[s * DM + d] = (v[r] - mu) * rstd * g[d] + b[d];
    }
}

// ---------------- host launch ----------------
//                BMODE BV4   RELU  CSKIP KCLIP
#define G_RM  (tc_gemm<0, true,  false, false, false>)
#define G_RMR (tc_gemm<0, true,  true,  false, false>)
#define G_HB  (tc_gemm<1, true,  false, false, false>)
#define G_SC  (tc_gemm<2, true,  false, true,  false>)
#define G_AV  (tc_gemm<0, true,  false, false, true >)
#define G_LG  (tc_gemm<0, false, false, false, false>)

extern "C" void kernel_launch(void* const* d_in, const int* in_sizes, int n_in,
                              void* d_out, int out_size)
{
    const int*   tokens = (const int*)  d_in[0];
    const float* emb    = (const float*)d_in[1];
    const float* Wq     = (const float*)d_in[2];
    const float* Wk     = (const float*)d_in[3];
    const float* Wv     = (const float*)d_in[4];
    const float* Wo     = (const float*)d_in[5];
    const float* bo     = (const float*)d_in[6];
    const float* ln1g   = (const float*)d_in[7];
    const float* ln1b   = (const float*)d_in[8];
    const float* W1     = (const float*)d_in[9];
    const float* b1     = (const float*)d_in[10];
    const float* W2     = (const float*)d_in[11];
    const float* b2     = (const float*)d_in[12];
    const float* ln2g   = (const float*)d_in[13];
    const float* ln2b   = (const float*)d_in[14];
    const float* Wout   = (const float*)d_in[15];
    const float* bout   = (const float*)d_in[16];
    float* out = (float*)d_out;

    cudaFuncSetAttribute(G_RM,  cudaFuncAttributeMaxDynamicSharedMemorySize, SMEMSZ);
    cudaFuncSetAttribute(G_RMR, cudaFuncAttributeMaxDynamicSharedMemorySize, SMEMSZ);
    cudaFuncSetAttribute(G_HB,  cudaFuncAttributeMaxDynamicSharedMemorySize, SMEMSZ);
    cudaFuncSetAttribute(G_SC,  cudaFuncAttributeMaxDynamicSharedMemorySize, SMEMSZ);
    cudaFuncSetAttribute(G_AV,  cudaFuncAttributeMaxDynamicSharedMemorySize, SMEMSZ);
    cudaFuncSetAttribute(G_LG,  cudaFuncAttributeMaxDynamicSharedMemorySize, SMEMSZ);

    float *x, *q, *k, *v, *attn, *mha, *ff, *t2;
    cudaGetSymbolAddress((void**)&x,    g_x);
    cudaGetSymbolAddress((void**)&q,    g_q);
    cudaGetSymbolAddress((void**)&k,    g_k);
    cudaGetSymbolAddress((void**)&v,    g_v);
    cudaGetSymbolAddress((void**)&attn, g_attn);
    cudaGetSymbolAddress((void**)&mha,  g_mha);
    cudaGetSymbolAddress((void**)&ff,   g_ff);
    cudaGetSymbolAddress((void**)&t2,   g_t2);

    embed_kernel<<<SEQ, 256>>>(tokens, emb);

    const dim3 blk(256);
    for (int l = 0; l < NB; ++l) {
        const float* Wql = Wq + (size_t)l * NH * DM * DH;
        const float* Wkl = Wk + (size_t)l * NH * DM * DH;
        const float* Wvl = Wv + (size_t)l * NH * DM * DH;

        // Q/K/V projections: [2048,1024] x head-blocked [1024,1024] -> [S, H*dh]
        G_HB<<<dim3(16, 16, 1), blk, SMEMSZ>>>(x, Wql, nullptr, q,
            DM, DM, DM, 0, DM, 0LL, 0LL, 0LL, 1.0f);
        G_HB<<<dim3(16, 16, 1), blk, SMEMSZ>>>(x, Wkl, nullptr, k,
            DM, DM, DM, 0, DM, 0LL, 0LL, 0LL, 1.0f);
        G_HB<<<dim3(16, 16, 1), blk, SMEMSZ>>>(x, Wvl, nullptr, v,
            DM, DM, DM, 0, DM, 0LL, 0LL, 0LL, 1.0f);

        // scores[h,s,t] = Q_h . K_h / 8  (causal tile-skip); A=q+h*64, B=k+h*64
        G_SC<<<dim3(32, 16, NH), blk, SMEMSZ>>>(q, k, nullptr, attn,
            SEQ, DH, DM, DM, SEQ, 64LL, 64LL, (long long)SEQ * SEQ, 0.125f);

        softmax_kernel<<<dim3(SEQ, NH), blk>>>();

        // heads = attn @ V  (K clipped causally), concat layout [S, H*dh]
        G_AV<<<dim3(1, 16, NH), blk, SMEMSZ>>>(attn, v, nullptr, mha,
            DH, SEQ, SEQ, DM, DM, (long long)SEQ * SEQ, 64LL, 64LL, 1.0f);

        // output projection + residual LN
        G_RM<<<dim3(16, 16, 1), blk, SMEMSZ>>>(mha, Wo + (size_t)l * DM * DM,
            bo + (size_t)l * DM, t2, DM, DM, DM, DM, DM, 0LL, 0LL, 0LL, 1.0f);
        ln_kernel<<<SEQ, blk>>>(t2, ln1g + (size_t)l * DM, ln1b + (size_t)l * DM);

        // FFN
        G_RMR<<<dim3(64, 16, 1), blk, SMEMSZ>>>(x, W1 + (size_t)l * DM * DFF,
            b1 + (size_t)l * DFF, ff, DFF, DM, DM, DFF, DFF, 0LL, 0LL, 0LL, 1.0f);
        G_RM<<<dim3(16, 16, 1), blk, SMEMSZ>>>(ff, W2 + (size_t)l * DFF * DM,
            b2 + (size_t)l * DM, t2, DM, DFF, DFF, DM, DM, 0LL, 0LL, 0LL, 1.0f);
        ln_kernel<<<SEQ, blk>>>(t2, ln2g + (size_t)l * DM, ln2b + (size_t)l * DM);
    }

    // final logits: [S, VOCAB] (ldb=50257 is unaligned -> scalar cp.async path)
    G_LG<<<dim3((VOCAB + 63) / 64, 16, 1), blk, SMEMSZ>>>(x, Wout, bout, out,
        VOCAB, DM, DM, VOCAB, VOCAB, 0LL, 0LL, 0LL, 1.0f);
}